// round 1
// baseline (speedup 1.0000x reference)
#include <cuda_runtime.h>
#include <cstdint>

// Problem constants (fixed by setup_inputs)
#define T_FRAMES   4096
#define E_FRAME    12288      // 4096 atoms * 3
#define TD_MAXX    512
#define N_ORIG     56         // t0 = 0,64,...,3520
#define NBLK       63         // frame blocks of 64: t in [0,4031]
#define EC         128        // elements per chunk
#define NCHUNK     (E_FRAME/EC)   // 96
#define CPB        8          // CTAs per frame-block (split element dim)
#define CPC        (NCHUNK/CPB)   // 12 chunks per CTA
#define XPITCH     132        // 128 + 4 pad: (132 % 32 == 4) -> conflict-free lane-strided LDS.128
#define NTHR       256

__device__ float gA[TD_MAXX];   // accumulates sum over (t0,t) of (S_t - 2*dot)
__device__ float gS0;           // accumulates sum over origins of S_t0

__global__ void msd_init() {
    if (threadIdx.x < TD_MAXX) gA[threadIdx.x] = 0.0f;
    if (threadIdx.x == 0) gS0 = 0.0f;
}

__device__ __forceinline__ void cp16(uint32_t dst, const void* src) {
    asm volatile("cp.async.cg.shared.global [%0], [%1], 16;" :: "r"(dst), "l"(src));
}

__global__ void __launch_bounds__(NTHR, 2) msd_main(const float* __restrict__ x) {
    __shared__ float x_s[64 * XPITCH];   // 64 frames x 128 elems (+pad)  33.0 KB
    __shared__ float o_s[8 * EC];        // up to 8 origin rows            4.0 KB
    __shared__ float red[64 * 9];        // per-(frame, origin|ss) CTA reduction

    const int tid = threadIdx.x;
    const int b   = blockIdx.x;
    const int k   = b / CPB;             // frame block: frames 64k..64k+63
    const int g   = b % CPB;             // element chunk-group
    const int o_lo = (k > 7) ? (k - 7) : 0;
    const int o_hi = (k < 55) ? k : 55;
    const int n_o  = o_hi - o_lo + 1;    // 1..8 valid origins

    const int w    = tid >> 5, lane = tid & 31;
    const int f    = ((w & 1) << 5) | lane;  // frame-in-block owned by this thread
    const int ev0  = (w >> 1) << 3;          // element subrange start, float4 units (8 per subrange)

    const uint32_t xs_base = (uint32_t)__cvta_generic_to_shared(x_s);
    const uint32_t os_base = (uint32_t)__cvta_generic_to_shared(o_s);

    // Register-resident accumulators: 8 origin dots (split even/odd for ILP) + sum-of-squares.
    float acc0[8], acc1[8];
    #pragma unroll
    for (int o = 0; o < 8; ++o) { acc0[o] = 0.0f; acc1[o] = 0.0f; }
    float ss0 = 0.0f, ss1 = 0.0f;

    for (int cc = 0; cc < CPC; ++cc) {
        const int cbase = (g * CPC + cc) * EC;

        // --- stage 64 frame rows (coalesced, cp.async 16B granules) ---
        #pragma unroll
        for (int j = 0; j < 8; ++j) {
            int i   = tid + j * NTHR;        // 0..2047
            int row = i >> 5;                // 32 granules per 128-float row
            int c16 = i & 31;
            const float* src = x + (size_t)(64 * k + row) * E_FRAME + cbase + (c16 << 2);
            cp16(xs_base + (uint32_t)(row * XPITCH + (c16 << 2)) * 4u, src);
        }
        // --- stage up to 8 origin rows ---
        {
            int o   = tid >> 5;              // 0..7
            int c16 = tid & 31;
            if (o < n_o) {
                const float* src = x + (size_t)(64 * (o_lo + o)) * E_FRAME + cbase + (c16 << 2);
                cp16(os_base + (uint32_t)(o * EC + (c16 << 2)) * 4u, src);
            } else {
                *(float4*)(o_s + o * EC + (c16 << 2)) = make_float4(0.f, 0.f, 0.f, 0.f);
            }
        }
        asm volatile("cp.async.commit_group;");
        asm volatile("cp.async.wait_group 0;");
        __syncthreads();

        // --- compute: lane == frame; origins broadcast from SMEM ---
        const float4* xr  = (const float4*)(x_s + f * XPITCH) + ev0;
        const float4* orp = (const float4*)(o_s) + ev0;
        #pragma unroll 4
        for (int v = 0; v < 8; ++v) {
            float4 xv = xr[v];
            ss0 = fmaf(xv.x, xv.x, ss0);
            ss1 = fmaf(xv.y, xv.y, ss1);
            ss0 = fmaf(xv.z, xv.z, ss0);
            ss1 = fmaf(xv.w, xv.w, ss1);
            #pragma unroll
            for (int o = 0; o < 8; ++o) {
                float4 ov = orp[(o << 5) + v];   // uniform address across warp -> broadcast
                acc0[o] = fmaf(xv.x, ov.x, acc0[o]);
                acc1[o] = fmaf(xv.y, ov.y, acc1[o]);
                acc0[o] = fmaf(xv.z, ov.z, acc0[o]);
                acc1[o] = fmaf(xv.w, ov.w, acc1[o]);
            }
        }
        __syncthreads();   // before overwriting staged tiles
    }

    // --- CTA reduction across the 4 element-subrange warp-groups ---
    for (int i = tid; i < 64 * 9; i += NTHR) red[i] = 0.0f;
    __syncthreads();
    atomicAdd(&red[f * 9 + 8], ss0 + ss1);
    #pragma unroll
    for (int o = 0; o < 8; ++o) atomicAdd(&red[f * 9 + o], acc0[o] + acc1[o]);
    __syncthreads();

    // --- scatter to global lag bins: td = (t) - 64*origin ---
    for (int p = tid; p < 512; p += NTHR) {
        int ff = p >> 3, o = p & 7;
        if (o < n_o) {
            int td = ((k - o_lo - o) << 6) + ff;     // in [0,511] by construction
            float val = red[ff * 9 + 8] - 2.0f * red[ff * 9 + o];
            atomicAdd(&gA[td], val);
        }
    }
    // S[t0] term (frame 64k is this block's first frame; contributes to every bin)
    if (tid == 0 && k <= 55) atomicAdd(&gS0, red[8]);   // red[f=0][ss]
}

__global__ void msd_fin(float* __restrict__ out) {
    int i = threadIdx.x;
    if (i < TD_MAXX) out[i] = (gA[i] + gS0) * (1.0f / (56.0f * 12288.0f));
}

extern "C" void kernel_launch(void* const* d_in, const int* in_sizes, int n_in,
                              void* d_out, int out_size) {
    const float* x = (const float*)d_in[0];
    float* out = (float*)d_out;
    msd_init<<<1, TD_MAXX>>>();
    msd_main<<<NBLK * CPB, NTHR>>>(x);
    msd_fin<<<1, TD_MAXX>>>(out);
}